// round 16
// baseline (speedup 1.0000x reference)
#include <cuda_runtime.h>
#include <cuda_bf16.h>
#include <cstdint>

#define NTOK 16384
#define HDIM 4096
#define NEXP 64
#define BM   128
#define KC   64
#define SPLITK 2
#define KSPAN (HDIM / SPLITK)        // 2048
#define NCHUNK (KSPAN / KC)          // 32
#define XS   (KC + 8)                // x smem row stride (floats) = 72
#define WS   (KC + 8)                // w smem row stride (bf16)  = 72
#define SMEM_X_BYTES (2 * BM * XS * 4)            // 73728
#define SMEM_W_BYTES (2 * NEXP * WS * 2)          // 18432 per array
#define SMEM_BYTES   (SMEM_X_BYTES + 2 * SMEM_W_BYTES)  // 110592 -> 2 CTAs/SM

#define FLT_MIN_NORMAL 1.17549435e-38f

// Pre-split W (fp32 -> bf16 hi + lo), 1 MB, L2-resident.
__device__ __nv_bfloat16 g_w_hi[NEXP * HDIM];
__device__ __nv_bfloat16 g_w_lo[NEXP * HDIM];
// Split-K partial logits [SPLITK][NTOK][NEXP] fp32 = 8 MB.
__device__ float g_part[SPLITK * NTOK * NEXP];

__global__ void prep_w_kernel(const float* __restrict__ w) {
    int i = blockIdx.x * blockDim.x + threadIdx.x;   // float4 granules
    if (i < NEXP * HDIM / 4) {
        float4 v = *reinterpret_cast<const float4*>(w + i * 4);
        __nv_bfloat162 h01 = __floats2bfloat162_rn(v.x, v.y);
        __nv_bfloat162 h23 = __floats2bfloat162_rn(v.z, v.w);
        __nv_bfloat162 l01 = __floats2bfloat162_rn(v.x - __bfloat162float(h01.x),
                                                   v.y - __bfloat162float(h01.y));
        __nv_bfloat162 l23 = __floats2bfloat162_rn(v.z - __bfloat162float(h23.x),
                                                   v.w - __bfloat162float(h23.y));
        *reinterpret_cast<uint2*>(g_w_hi + i * 4) =
            make_uint2(*reinterpret_cast<uint32_t*>(&h01),
                       *reinterpret_cast<uint32_t*>(&h23));
        *reinterpret_cast<uint2*>(g_w_lo + i * 4) =
            make_uint2(*reinterpret_cast<uint32_t*>(&l01),
                       *reinterpret_cast<uint32_t*>(&l23));
    }
}

__device__ __forceinline__ void mma_bf16(float* c, const uint32_t* a,
                                         uint32_t b0, uint32_t b1) {
    asm volatile(
        "mma.sync.aligned.m16n8k16.row.col.f32.bf16.bf16.f32 "
        "{%0,%1,%2,%3}, {%4,%5,%6,%7}, {%8,%9}, {%0,%1,%2,%3};\n"
        : "+f"(c[0]), "+f"(c[1]), "+f"(c[2]), "+f"(c[3])
        : "r"(a[0]), "r"(a[1]), "r"(a[2]), "r"(a[3]), "r"(b0), "r"(b1));
}

__device__ __forceinline__ void cvt_split(float2 f, uint32_t& hi, uint32_t& lo) {
    __nv_bfloat162 h = __floats2bfloat162_rn(f.x, f.y);
    float rx = f.x - __bfloat162float(h.x);
    float ry = f.y - __bfloat162float(h.y);
    __nv_bfloat162 l = __floats2bfloat162_rn(rx, ry);
    hi = *reinterpret_cast<uint32_t*>(&h);
    lo = *reinterpret_cast<uint32_t*>(&l);
}

__device__ __forceinline__ void cp16(void* smem_dst, const void* gmem_src) {
    uint32_t s = (uint32_t)__cvta_generic_to_shared(smem_dst);
    asm volatile("cp.async.cg.shared.global [%0], [%1], 16;\n" :: "r"(s), "l"(gmem_src));
}

__device__ __forceinline__ uint32_t f2sortable(float f) {
    uint32_t b = __float_as_uint(f);
    return b ^ (((int32_t)b >> 31) | 0x80000000u);
}
__device__ __forceinline__ float sortable2f(uint32_t k) {
    uint32_t b = (k & 0x80000000u) ? (k ^ 0x80000000u) : ~k;
    return __uint_as_float(b);
}

// ---- GEMM: R15 pipeline; 4x2 warp partition (W fragments reused across 2 m-tiles) ----
__global__ __launch_bounds__(256, 2)
void gate_gemm_kernel(const float* __restrict__ x) {
    extern __shared__ char smem[];
    float* xs = reinterpret_cast<float*>(smem);                       // [2][BM][XS]
    __nv_bfloat16* wh = reinterpret_cast<__nv_bfloat16*>(smem + SMEM_X_BYTES); // [2][NEXP][WS]
    __nv_bfloat16* wl = wh + 2 * NEXP * WS;

    const int tid  = threadIdx.x;
    const int warp = tid >> 5;
    const int lane = tid & 31;
    const int g    = lane >> 2;
    const int tg   = lane & 3;
    const int mg   = warp >> 1;       // m-group: rows mg*32 .. +31
    const int eg   = warp & 1;        // e-group: experts eg*32 .. +31
    const int tile  = blockIdx.x >> 1;
    const int split = blockIdx.x & 1;
    const int mBase = tile * BM;
    const int kBase = split * KSPAN;

    float acc[8][4];                   // [mt*4 + nt][frag]
#pragma unroll
    for (int i = 0; i < 8; i++)
#pragma unroll
        for (int j = 0; j < 4; j++) acc[i][j] = 0.f;

    auto issue_stage = [&](int c, int slot) {
        const int k0 = kBase + c * KC;
        float* xb = xs + slot * BM * XS;
#pragma unroll
        for (int i = 0; i < 8; i++) {                 // 128 rows x 16 float4
            int idx = tid + i * 256;
            int row = idx >> 4, c4 = idx & 15;
            cp16(xb + row * XS + c4 * 4,
                 x + (size_t)(mBase + row) * HDIM + k0 + c4 * 4);
        }
        __nv_bfloat16* whb = wh + slot * NEXP * WS;
        __nv_bfloat16* wlb = wl + slot * NEXP * WS;
#pragma unroll
        for (int i = 0; i < 2; i++) {                 // 64 rows x 8 granules
            int idx = tid + i * 256;
            int row = idx >> 3, q = idx & 7;
            cp16(whb + row * WS + q * 8, g_w_hi + (size_t)row * HDIM + k0 + q * 8);
            cp16(wlb + row * WS + q * 8, g_w_lo + (size_t)row * HDIM + k0 + q * 8);
        }
        asm volatile("cp.async.commit_group;\n" ::: "memory");
    };

    issue_stage(0, 0);
    issue_stage(1, 1);
    asm volatile("cp.async.wait_group 1;\n" ::: "memory");
    __syncthreads();

    for (int c = 0; c < NCHUNK; c++) {
        const int buf = c & 1;

        const float* xb = xs + buf * BM * XS + mg * 32 * XS;
        const __nv_bfloat16* whb = wh + buf * NEXP * WS;
        const __nv_bfloat16* wlb = wl + buf * NEXP * WS;

#pragma unroll
        for (int ks = 0; ks < KC / 16; ks++) {
            const int k0 = ks * 16;
            uint32_t ah[2][4], al[2][4];
#pragma unroll
            for (int mt = 0; mt < 2; mt++) {
                const float* xr = xb + mt * 16 * XS;
                float2 f00 = *reinterpret_cast<const float2*>(xr + g * XS + k0 + tg * 2);
                float2 f01 = *reinterpret_cast<const float2*>(xr + g * XS + k0 + tg * 2 + 8);
                float2 f10 = *reinterpret_cast<const float2*>(xr + (g + 8) * XS + k0 + tg * 2);
                float2 f11 = *reinterpret_cast<const float2*>(xr + (g + 8) * XS + k0 + tg * 2 + 8);
                cvt_split(f00, ah[mt][0], al[mt][0]);
                cvt_split(f10, ah[mt][1], al[mt][1]);
                cvt_split(f01, ah[mt][2], al[mt][2]);
                cvt_split(f11, ah[mt][3], al[mt][3]);
            }
#pragma unroll
            for (int nt = 0; nt < 4; nt++) {
                const int e = eg * 32 + nt * 8 + g;
                uint32_t bh0 = *reinterpret_cast<const uint32_t*>(whb + e * WS + k0 + tg * 2);
                uint32_t bh1 = *reinterpret_cast<const uint32_t*>(whb + e * WS + k0 + tg * 2 + 8);
                uint32_t bl0 = *reinterpret_cast<const uint32_t*>(wlb + e * WS + k0 + tg * 2);
                uint32_t bl1 = *reinterpret_cast<const uint32_t*>(wlb + e * WS + k0 + tg * 2 + 8);
                // W fragments reused across both m-tiles (halves W smem reads)
                mma_bf16(acc[nt],     ah[0], bh0, bh1);
                mma_bf16(acc[4 + nt], ah[1], bh0, bh1);
                mma_bf16(acc[nt],     ah[0], bl0, bl1);
                mma_bf16(acc[4 + nt], ah[1], bl0, bl1);
                mma_bf16(acc[nt],     al[0], bh0, bh1);
                mma_bf16(acc[4 + nt], al[1], bh0, bh1);
            }
        }
        __syncthreads();

        if (c + 2 < NCHUNK) {
            issue_stage(c + 2, buf);
            asm volatile("cp.async.wait_group 1;\n" ::: "memory");
            __syncthreads();
        } else if (c + 1 < NCHUNK) {
            asm volatile("cp.async.wait_group 0;\n" ::: "memory");
            __syncthreads();
        }
    }

    // write fp32 partial logits for this K-half
    float* p = g_part + (size_t)split * NTOK * NEXP;
#pragma unroll
    for (int mt = 0; mt < 2; mt++) {
        const int n0 = mBase + mg * 32 + mt * 16 + g;
        const int n1 = n0 + 8;
#pragma unroll
        for (int nt = 0; nt < 4; nt++) {
            const int e = eg * 32 + nt * 8 + tg * 2;
            *reinterpret_cast<float2*>(p + (size_t)n0 * NEXP + e) =
                make_float2(acc[mt * 4 + nt][0], acc[mt * 4 + nt][1]);
            *reinterpret_cast<float2*>(p + (size_t)n1 * NEXP + e) =
                make_float2(acc[mt * 4 + nt][2], acc[mt * 4 + nt][3]);
        }
    }
}

// ---- reduce: partials + noise -> FTZ softmax + top-2 (proven) ----
__global__ __launch_bounds__(256)
void gate_reduce_kernel(const float* __restrict__ noise,
                        float* __restrict__ out) {
    const int n = blockIdx.x * 256 + threadIdx.x;
    if (n >= NTOK) return;

    float v[NEXP];
#pragma unroll
    for (int q = 0; q < NEXP / 4; q++) {
        float4 a = *reinterpret_cast<const float4*>(g_part + (size_t)n * NEXP + q * 4);
        float4 b = *reinterpret_cast<const float4*>(
            g_part + (size_t)NTOK * NEXP + (size_t)n * NEXP + q * 4);
        float4 nz = *reinterpret_cast<const float4*>(noise + (size_t)n * NEXP + q * 4);
        v[q * 4 + 0] = a.x + b.x + nz.x;
        v[q * 4 + 1] = a.y + b.y + nz.y;
        v[q * 4 + 2] = a.z + b.z + nz.z;
        v[q * 4 + 3] = a.w + b.w + nz.w;
    }

    // FTZ/DAZ softmax semantics (XLA:CPU ScopedFlushDenormal): score flushes
    // to exactly 0 when fl(exp(d))/s is subnormal, i.e. exp(d) < FLT_MIN * s;
    // flushed experts tie at 0 -> lowest index wins (jax top_k). Above the
    // flush line score order == order of d.
    float m = -3.4e38f;
#pragma unroll 8
    for (int e = 0; e < NEXP; e++) m = fmaxf(m, v[e]);
    float s = 0.f;
#pragma unroll 8
    for (int e = 0; e < NEXP; e++) s += __expf(v[e] - m);
    const float flushLim = FLT_MIN_NORMAL * s;

    unsigned long long k1 = 0ull, k2 = 0ull;
#pragma unroll 8
    for (int e = 0; e < NEXP; e++) {
        float d = v[e] - m;
        float ed = __expf(d);
        uint32_t k32 = (ed < flushLim) ? 0u : f2sortable(d);
        unsigned long long key =
            ((unsigned long long)k32 << 32) | (unsigned long long)(64 - e);
        if (key > k1) { k2 = k1; k1 = key; }
        else if (key > k2) { k2 = key; }
    }

    int i1 = 64 - (int)(k1 & 0xffffffffull);
    int i2 = 64 - (int)(k2 & 0xffffffffull);
    uint32_t h1 = (uint32_t)(k1 >> 32), h2 = (uint32_t)(k2 >> 32);
    float inv = 1.0f / s;
    float w1 = (h1 == 0u) ? 0.f : __expf(sortable2f(h1)) * inv;
    float w2 = (h2 == 0u) ? 0.f : __expf(sortable2f(h2)) * inv;
    // layout: [topk_idx as float (N*2)] then [topk_weight (N*2)]
    *reinterpret_cast<float2*>(out + 2 * n) = make_float2((float)i1, (float)i2);
    *reinterpret_cast<float2*>(out + 2 * NTOK + 2 * n) = make_float2(w1, w2);
}

extern "C" void kernel_launch(void* const* d_in, const int* in_sizes, int n_in,
                              void* d_out, int out_size) {
    const float* x     = (const float*)d_in[0];  // hidden_states [4,4096,4096]
    const float* w     = (const float*)d_in[1];  // weight [64,4096]
    const float* noise = (const float*)d_in[2];  // noise [16384,64]
    float* out = (float*)d_out;

    cudaFuncSetAttribute(gate_gemm_kernel,
                         cudaFuncAttributeMaxDynamicSharedMemorySize, SMEM_BYTES);

    prep_w_kernel<<<(NEXP * HDIM / 4 + 255) / 256, 256>>>(w);
    gate_gemm_kernel<<<(NTOK / BM) * SPLITK, 256, SMEM_BYTES>>>(x);
    gate_reduce_kernel<<<NTOK / 256, 256>>>(noise, out);
}